// round 2
// baseline (speedup 1.0000x reference)
#include <cuda_runtime.h>
#include <cstdint>
#include <cstddef>

// Problem constants
#define BATCH 4
#define NPTS  16384      // fine points per batch
#define SPTS  4096       // coarse points per batch
#define CF    128        // fine feat channels
#define CC    256        // coarse feat channels
#define CIN   384        // CF + CC
#define CMID  192
#define COUT  128
#define GROUPS 8
#define EPS_GN 1e-5f
#define EPS_D  1e-8f

#define BN_TOTAL (BATCH * NPTS)   // 65536

// -------------------- scratch (device globals; no allocation) --------------------
__device__ float g_combined[(size_t)BN_TOTAL * CIN];   // 100.7 MB
__device__ float g_h1[(size_t)BN_TOTAL * CMID];        // 50.3 MB
__device__ int   g_idx[(size_t)BN_TOTAL * 3];
__device__ float g_wt[(size_t)BN_TOTAL * 3];

#define NCHUNKS 32
__device__ float g_part1[BATCH * GROUPS * NCHUNKS * 2];
__device__ float g_part2[BATCH * GROUPS * NCHUNKS * 2];
__device__ float g_a1[BATCH * CMID], g_b1[BATCH * CMID];
__device__ float g_a2[BATCH * COUT], g_b2[BATCH * COUT];

// ==================== Kernel 1: kNN (K=3) + IDW weights ====================
// grid: (NPTS/128, BATCH), block 128.
#define KNN_CHUNK 2048
__global__ void __launch_bounds__(128) knn_kernel(
    const float* __restrict__ fxyz, const float* __restrict__ cxyz,
    int* __restrict__ oidx, float* __restrict__ owt)
{
    __shared__ float4 cs[KNN_CHUNK];   // 32 KB
    const int b = blockIdx.y;
    const int n = blockIdx.x * 128 + threadIdx.x;

    const float* fp = fxyz + ((size_t)b * NPTS + n) * 3;
    const float qx = fp[0], qy = fp[1], qz = fp[2];
    const float qn = qx*qx + qy*qy + qz*qz;

    float s0 = 3.4e38f, s1 = 3.4e38f, s2 = 3.4e38f;
    int   i0 = 0, i1 = 0, i2 = 0;

    for (int c0 = 0; c0 < SPTS; c0 += KNN_CHUNK) {
        __syncthreads();
        for (int j = threadIdx.x; j < KNN_CHUNK; j += 128) {
            const float* cp = cxyz + ((size_t)b * SPTS + c0 + j) * 3;
            float x = cp[0], y = cp[1], z = cp[2];
            cs[j] = make_float4(x, y, z, x*x + y*y + z*z);
        }
        __syncthreads();
        #pragma unroll 8
        for (int j = 0; j < KNN_CHUNK; j++) {
            float4 c = cs[j];
            float dot = qx*c.x + qy*c.y + qz*c.z;
            // same ranking formula as the reference: ||a||^2 + ||b||^2 - 2 a.b
            float score = fmaf(-2.0f, dot, qn + c.w);
            if (score < s2) {
                int idx = c0 + j;
                if (score < s1) {
                    s2 = s1; i2 = i1;
                    if (score < s0) { s1 = s0; i1 = i0; s0 = score; i0 = idx; }
                    else            { s1 = score; i1 = idx; }
                } else { s2 = score; i2 = idx; }
            }
        }
    }

    // exact distance recompute (matches reference's dist2 = max(sum(diff^2), eps))
    int   ii[3] = { i0, i1, i2 };
    float w[3];
    float wsum = 0.0f;
    #pragma unroll
    for (int k = 0; k < 3; k++) {
        const float* cp = cxyz + ((size_t)b * SPTS + ii[k]) * 3;
        float dx = qx - cp[0], dy = qy - cp[1], dz = qz - cp[2];
        float d2 = fmaxf(dx*dx + dy*dy + dz*dz, EPS_D);
        w[k] = 1.0f / d2;
        wsum += w[k];
    }
    float inv = 1.0f / wsum;
    size_t base = ((size_t)b * NPTS + n) * 3;
    #pragma unroll
    for (int k = 0; k < 3; k++) {
        oidx[base + k] = ii[k];
        owt [base + k] = w[k] * inv;
    }
}

// ==================== Kernel 2: interp + concat -> combined ====================
// one warp per point; block 256 = 8 points; grid BN_TOTAL/8
__global__ void __launch_bounds__(256) interp_kernel(
    const float* __restrict__ ffeat, const float* __restrict__ cfeat,
    const int* __restrict__ idx, const float* __restrict__ wt,
    float* __restrict__ comb)
{
    const int gwarp = (blockIdx.x * 256 + threadIdx.x) >> 5;
    const int lane  = threadIdx.x & 31;
    const size_t p  = (size_t)gwarp;          // global point 0..65535
    const int b     = (int)(p >> 14);

    const int*   ip = idx + p * 3;
    const float* wp = wt  + p * 3;
    int   j0 = ip[0], j1 = ip[1], j2 = ip[2];
    float w0 = wp[0], w1 = wp[1], w2 = wp[2];

    float4*       out = (float4*)(comb + p * CIN);
    const float4* f4  = (const float4*)(ffeat + p * CF);
    out[lane] = f4[lane];                      // channels [0,128): copy fine_feat

    const float4* c0 = (const float4*)(cfeat + ((size_t)b * SPTS + j0) * CC);
    const float4* c1 = (const float4*)(cfeat + ((size_t)b * SPTS + j1) * CC);
    const float4* c2 = (const float4*)(cfeat + ((size_t)b * SPTS + j2) * CC);

    #pragma unroll
    for (int t = 0; t < 2; t++) {
        int c = t * 32 + lane;                 // 0..63 float4 -> 256 channels
        float4 A = c0[c], B = c1[c], Cv = c2[c];
        float4 r;
        r.x = w0*A.x + w1*B.x + w2*Cv.x;
        r.y = w0*A.y + w1*B.y + w2*Cv.y;
        r.z = w0*A.z + w1*B.z + w2*Cv.z;
        r.w = w0*A.w + w1*B.w + w2*Cv.w;
        out[32 + c] = r;
    }
}

// ==================== Kernel 3/6: tiled fp32 GEMM ====================
// C[rows, M] = act(A)[rows, K] @ W[M, K]^T
// act = identity (TRANS=false) or per-(batch,channel) scale/bias + ReLU (TRANS=true)
// BM=128, BN=64, BK=16, 256 threads, 8x4 per-thread tile.
template<bool TRANS>
__global__ void __launch_bounds__(256) gemm_kernel(
    const float* __restrict__ A, const float* __restrict__ W, float* __restrict__ C,
    int K, int M, const float* __restrict__ ac, const float* __restrict__ bc)
{
    constexpr int BM = 128, BN = 64, BK = 16;
    __shared__ float As[BK][BM];
    __shared__ float Bs[BK][BN];

    const int n0  = blockIdx.x * BM;
    const int m0  = blockIdx.y * BN;
    const int tid = threadIdx.x;
    const int arow0 = tid >> 2, akq = tid & 3;   // A loads: 2 x float4 per thread
    const int brow  = tid >> 2, bkq = tid & 3;   // B loads: 1 x float4 per thread
    const int tr = tid >> 4;                      // 0..15 (row group of 8)
    const int tc = tid & 15;                      // 0..15 (col group of 4)

    float4 aReg[2], bReg;

    auto ldA = [&](int k0) {
        #pragma unroll
        for (int u = 0; u < 2; u++) {
            int row = arow0 + u * 64;
            int gn  = n0 + row;
            float4 v = *(const float4*)(A + (size_t)gn * K + k0 + akq * 4);
            if (TRANS) {
                int bb = gn >> 14;
                const float* ap = ac + bb * K + k0 + akq * 4;
                const float* bp = bc + bb * K + k0 + akq * 4;
                v.x = fmaxf(fmaf(v.x, ap[0], bp[0]), 0.0f);
                v.y = fmaxf(fmaf(v.y, ap[1], bp[1]), 0.0f);
                v.z = fmaxf(fmaf(v.z, ap[2], bp[2]), 0.0f);
                v.w = fmaxf(fmaf(v.w, ap[3], bp[3]), 0.0f);
            }
            aReg[u] = v;
        }
    };
    auto ldB = [&](int k0) {
        bReg = *(const float4*)(W + (size_t)(m0 + brow) * K + k0 + bkq * 4);
    };

    ldA(0); ldB(0);

    float acc[8][4] = {};
    const int nK = K / BK;
    for (int kt = 0; kt < nK; kt++) {
        // store staged tiles (transposed to k-major)
        #pragma unroll
        for (int u = 0; u < 2; u++) {
            int row = arow0 + u * 64;
            As[akq*4 + 0][row] = aReg[u].x;
            As[akq*4 + 1][row] = aReg[u].y;
            As[akq*4 + 2][row] = aReg[u].z;
            As[akq*4 + 3][row] = aReg[u].w;
        }
        Bs[bkq*4 + 0][brow] = bReg.x;
        Bs[bkq*4 + 1][brow] = bReg.y;
        Bs[bkq*4 + 2][brow] = bReg.z;
        Bs[bkq*4 + 3][brow] = bReg.w;
        __syncthreads();

        if (kt + 1 < nK) { ldA((kt + 1) * BK); ldB((kt + 1) * BK); }

        #pragma unroll
        for (int kk = 0; kk < BK; kk++) {
            float4 a0 = *(const float4*)&As[kk][tr * 8];
            float4 a1 = *(const float4*)&As[kk][tr * 8 + 4];
            float4 b0 = *(const float4*)&Bs[kk][tc * 4];
            float av[8] = { a0.x,a0.y,a0.z,a0.w, a1.x,a1.y,a1.z,a1.w };
            float bv[4] = { b0.x,b0.y,b0.z,b0.w };
            #pragma unroll
            for (int i = 0; i < 8; i++)
                #pragma unroll
                for (int j = 0; j < 4; j++)
                    acc[i][j] = fmaf(av[i], bv[j], acc[i][j]);
        }
        __syncthreads();
    }

    #pragma unroll
    for (int i = 0; i < 8; i++) {
        float4 v = make_float4(acc[i][0], acc[i][1], acc[i][2], acc[i][3]);
        *(float4*)(C + (size_t)(n0 + tr * 8 + i) * M + m0 + tc * 4) = v;
    }
}

// ==================== GroupNorm stats: partial then final ====================
// partial: grid (NCHUNKS, BATCH*GROUPS), block 256
template<int CPG>
__global__ void __launch_bounds__(256) stats_partial(
    const float* __restrict__ h, int Cdim, float* __restrict__ part)
{
    const int chunk = blockIdx.x;
    const int bg    = blockIdx.y;
    const int b = bg >> 3, g = bg & 7;
    const int nPer = NPTS / NCHUNKS;          // 512
    const int n0 = chunk * nPer;
    const int total = nPer * CPG;
    const int tid = threadIdx.x;

    float s = 0.0f, ss = 0.0f;
    for (int i = tid; i < total; i += 256) {
        int n = n0 + i / CPG;
        int c = g * CPG + i % CPG;
        float v = h[((size_t)(b << 14) + n) * Cdim + c];
        s += v; ss += v * v;
    }
    __shared__ float sh[512];
    sh[tid] = s; sh[tid + 256] = ss;
    __syncthreads();
    for (int off = 128; off > 0; off >>= 1) {
        if (tid < off) { sh[tid] += sh[tid + off]; sh[256 + tid] += sh[256 + tid + off]; }
        __syncthreads();
    }
    if (tid == 0) {
        part[(bg * NCHUNKS + chunk) * 2 + 0] = sh[0];
        part[(bg * NCHUNKS + chunk) * 2 + 1] = sh[256];
    }
}

// final: grid BATCH*GROUPS, block CPG. Computes per-channel affine (a, b) folding GN.
template<int CPG>
__global__ void stats_final(
    const float* __restrict__ part, const float* __restrict__ gamma,
    const float* __restrict__ beta, float* __restrict__ acoef,
    float* __restrict__ bcoef, int Cdim)
{
    const int bg = blockIdx.x;
    const int b = bg >> 3, g = bg & 7;
    __shared__ float s_mean, s_istd;
    if (threadIdx.x == 0) {
        float s = 0.0f, ss = 0.0f;
        for (int i = 0; i < NCHUNKS; i++) {       // fixed-order: deterministic
            s  += part[(bg * NCHUNKS + i) * 2 + 0];
            ss += part[(bg * NCHUNKS + i) * 2 + 1];
        }
        float cnt = (float)NPTS * (float)CPG;
        float mu  = s / cnt;
        float var = ss / cnt - mu * mu;
        s_mean = mu;
        s_istd = rsqrtf(var + EPS_GN);
    }
    __syncthreads();
    int ch = g * CPG + threadIdx.x;
    float a = gamma[ch] * s_istd;
    acoef[b * Cdim + ch] = a;
    bcoef[b * Cdim + ch] = beta[ch] - s_mean * a;
}

// ==================== finalize: out = relu(h2 * a2 + b2) in place ====================
__global__ void __launch_bounds__(256) finalize_kernel(
    float* __restrict__ out, const float* __restrict__ a, const float* __restrict__ bc)
{
    size_t i = (size_t)blockIdx.x * 256 + threadIdx.x;   // 8,388,608 total
    int c = (int)(i & 127);
    int b = (int)(i >> 21);                               // 16384*128 = 2^21
    float v = out[i];
    out[i] = fmaxf(fmaf(v, a[b * COUT + c], bc[b * COUT + c]), 0.0f);
}

// ==================== launch ====================
extern "C" void kernel_launch(void* const* d_in, const int* in_sizes, int n_in,
                              void* d_out, int out_size)
{
    const float* fine_xyz    = (const float*)d_in[0];
    const float* coarse_xyz  = (const float*)d_in[1];
    const float* fine_feat   = (const float*)d_in[2];
    const float* coarse_feat = (const float*)d_in[3];
    const float* w1          = (const float*)d_in[4];
    const float* g1_w        = (const float*)d_in[5];
    const float* g1_b        = (const float*)d_in[6];
    const float* w2          = (const float*)d_in[7];
    const float* g2_w        = (const float*)d_in[8];
    const float* g2_b        = (const float*)d_in[9];
    float* out = (float*)d_out;

    float* combined; cudaGetSymbolAddress((void**)&combined, g_combined);
    float* h1;       cudaGetSymbolAddress((void**)&h1, g_h1);
    int*   idx;      cudaGetSymbolAddress((void**)&idx, g_idx);
    float* wt;       cudaGetSymbolAddress((void**)&wt, g_wt);
    float* part1;    cudaGetSymbolAddress((void**)&part1, g_part1);
    float* part2;    cudaGetSymbolAddress((void**)&part2, g_part2);
    float* a1;       cudaGetSymbolAddress((void**)&a1, g_a1);
    float* b1;       cudaGetSymbolAddress((void**)&b1, g_b1);
    float* a2;       cudaGetSymbolAddress((void**)&a2, g_a2);
    float* b2;       cudaGetSymbolAddress((void**)&b2, g_b2);

    // 1) kNN + weights
    knn_kernel<<<dim3(NPTS / 128, BATCH), 128>>>(fine_xyz, coarse_xyz, idx, wt);

    // 2) interpolate + concat
    interp_kernel<<<BN_TOTAL / 8, 256>>>(fine_feat, coarse_feat, idx, wt, combined);

    // 3) GEMM1: h1 = combined @ w1^T
    gemm_kernel<false><<<dim3(BN_TOTAL / 128, CMID / 64), 256>>>(
        combined, w1, h1, CIN, CMID, nullptr, nullptr);

    // 4-5) GN1 stats -> per-channel affine
    stats_partial<CMID / GROUPS><<<dim3(NCHUNKS, BATCH * GROUPS), 256>>>(h1, CMID, part1);
    stats_final<CMID / GROUPS><<<BATCH * GROUPS, CMID / GROUPS>>>(part1, g1_w, g1_b, a1, b1, CMID);

    // 6) GEMM2: h2 = relu(gn1(h1)) @ w2^T  (norm+relu fused into A-load); raw h2 -> d_out
    gemm_kernel<true><<<dim3(BN_TOTAL / 128, COUT / 64), 256>>>(
        h1, w2, out, CMID, COUT, a1, b1);

    // 7-8) GN2 stats
    stats_partial<COUT / GROUPS><<<dim3(NCHUNKS, BATCH * GROUPS), 256>>>(out, COUT, part2);
    stats_final<COUT / GROUPS><<<BATCH * GROUPS, COUT / GROUPS>>>(part2, g2_w, g2_b, a2, b2, COUT);

    // 9) final normalize + relu (in place on d_out)
    finalize_kernel<<<(BN_TOTAL * COUT) / 256, 256>>>(out, a2, b2);
}

// round 4
// speedup vs baseline: 1.2730x; 1.2730x over previous
#include <cuda_runtime.h>
#include <cuda_fp16.h>
#include <cstdint>
#include <cstddef>

// Problem constants
#define BATCH 4
#define NPTS  16384
#define SPTS  4096
#define CF    128
#define CC    256
#define CIN   384
#define CMID  192
#define COUT  128
#define GROUPS 8
#define EPS_GN 1e-5f
#define EPS_D  1e-8f
#define BN_TOTAL (BATCH * NPTS)   // 65536
#define CTAS_PER_BATCH 128

// -------------------- scratch (device globals; no allocation) --------------------
__device__ __align__(16) __half g_comb_hi[(size_t)BN_TOTAL * CIN];  // 50.3 MB
__device__ __align__(16) __half g_comb_lo[(size_t)BN_TOTAL * CIN];  // 50.3 MB
__device__ __align__(16) float  g_h1[(size_t)BN_TOTAL * CMID];      // 50.3 MB
__device__ int   g_idx[(size_t)BN_TOTAL * 3];
__device__ float g_wt[(size_t)BN_TOTAL * 3];
__device__ __align__(16) __half g_w1h[CMID * CIN], g_w1l[CMID * CIN];
__device__ __align__(16) __half g_w2h[COUT * CMID], g_w2l[COUT * CMID];
// per-CTA partial GN stats: [0..4095] sums, [4096..8191] sumsq; index (bg*128 + cta)
__device__ float g_part1[2 * 32 * CTAS_PER_BATCH];
__device__ float g_part2[2 * 32 * CTAS_PER_BATCH];
__device__ float g_a1[BATCH * CMID], g_b1[BATCH * CMID];
__device__ float g_a2[BATCH * COUT], g_b2[BATCH * COUT];

// ==================== helpers ====================
__device__ __forceinline__ uint32_t smem_u32(const void* p) {
    uint32_t a;
    asm("{ .reg .u64 t; cvta.to.shared.u64 t, %1; cvt.u32.u64 %0, t; }" : "=r"(a) : "l"(p));
    return a;
}
#define LDSM4(r0, r1, r2, r3, addr) \
    asm volatile("ldmatrix.sync.aligned.m8n8.x4.shared.b16 {%0,%1,%2,%3}, [%4];" \
        : "=r"(r0), "=r"(r1), "=r"(r2), "=r"(r3) : "r"(addr))
#define MMA16816(d, a0, a1, a2, a3, b0, b1) \
    asm volatile("mma.sync.aligned.m16n8k16.row.col.f32.f16.f16.f32 " \
        "{%0,%1,%2,%3},{%4,%5,%6,%7},{%8,%9},{%0,%1,%2,%3};" \
        : "+f"((d)[0]), "+f"((d)[1]), "+f"((d)[2]), "+f"((d)[3]) \
        : "r"(a0), "r"(a1), "r"(a2), "r"(a3), "r"(b0), "r"(b1))

// fp16 hi/lo split of two floats, packed as half2 words
__device__ __forceinline__ void split2(float x, float y, uint32_t& h, uint32_t& l) {
    __half hx = __float2half_rn(x), hy = __float2half_rn(y);
    __half lx = __float2half_rn(x - __half2float(hx));
    __half ly = __float2half_rn(y - __half2float(hy));
    h = ((uint32_t)__half_as_ushort(hy) << 16) | __half_as_ushort(hx);
    l = ((uint32_t)__half_as_ushort(ly) << 16) | __half_as_ushort(lx);
}

// ==================== Kernel 1: kNN (K=3) + IDW weights ====================
#define KNN_CHUNK 2048
__global__ void __launch_bounds__(128) knn_kernel(
    const float* __restrict__ fxyz, const float* __restrict__ cxyz,
    int* __restrict__ oidx, float* __restrict__ owt)
{
    __shared__ float4 cs[KNN_CHUNK];
    const int b = blockIdx.y;
    const int n = blockIdx.x * 128 + threadIdx.x;
    const float* fp = fxyz + ((size_t)b * NPTS + n) * 3;
    const float qx = fp[0], qy = fp[1], qz = fp[2];
    const float qn = qx*qx + qy*qy + qz*qz;

    float s0 = 3.4e38f, s1 = 3.4e38f, s2 = 3.4e38f;
    int   i0 = 0, i1 = 0, i2 = 0;

    for (int c0 = 0; c0 < SPTS; c0 += KNN_CHUNK) {
        __syncthreads();
        for (int j = threadIdx.x; j < KNN_CHUNK; j += 128) {
            const float* cp = cxyz + ((size_t)b * SPTS + c0 + j) * 3;
            float x = cp[0], y = cp[1], z = cp[2];
            cs[j] = make_float4(x, y, z, x*x + y*y + z*z);
        }
        __syncthreads();
        #pragma unroll 8
        for (int j = 0; j < KNN_CHUNK; j++) {
            float4 c = cs[j];
            float dot = qx*c.x + qy*c.y + qz*c.z;
            float score = fmaf(-2.0f, dot, qn + c.w);   // reference ranking formula
            if (score < s2) {
                int idx = c0 + j;
                if (score < s1) {
                    s2 = s1; i2 = i1;
                    if (score < s0) { s1 = s0; i1 = i0; s0 = score; i0 = idx; }
                    else            { s1 = score; i1 = idx; }
                } else { s2 = score; i2 = idx; }
            }
        }
    }
    int ii[3] = { i0, i1, i2 };
    float w[3], wsum = 0.0f;
    #pragma unroll
    for (int k = 0; k < 3; k++) {
        const float* cp = cxyz + ((size_t)b * SPTS + ii[k]) * 3;
        float dx = qx - cp[0], dy = qy - cp[1], dz = qz - cp[2];
        float d2 = fmaxf(dx*dx + dy*dy + dz*dz, EPS_D);
        w[k] = 1.0f / d2; wsum += w[k];
    }
    float inv = 1.0f / wsum;
    size_t base = ((size_t)b * NPTS + n) * 3;
    #pragma unroll
    for (int k = 0; k < 3; k++) { oidx[base + k] = ii[k]; owt[base + k] = w[k] * inv; }
}

// ==================== Kernel 2: weights fp32 -> fp16 hi/lo ====================
__global__ void prep_weights(const float* __restrict__ w1, const float* __restrict__ w2,
                             __half* w1h, __half* w1l, __half* w2h, __half* w2l)
{
    int i = blockIdx.x * 256 + threadIdx.x;
    if (i < CMID * CIN) {
        float x = w1[i];
        __half h = __float2half_rn(x);
        w1h[i] = h; w1l[i] = __float2half_rn(x - __half2float(h));
    }
    int j = i - CMID * CIN;
    if (j >= 0 && j < COUT * CMID) {
        float x = w2[j];
        __half h = __float2half_rn(x);
        w2h[j] = h; w2l[j] = __float2half_rn(x - __half2float(h));
    }
}

// ==================== Kernel 3: interp + concat -> fp16 hi/lo combined ====================
__global__ void __launch_bounds__(256) interp_kernel(
    const float* __restrict__ ffeat, const float* __restrict__ cfeat,
    const int* __restrict__ idx, const float* __restrict__ wt,
    __half* __restrict__ chi, __half* __restrict__ clo)
{
    const int gwarp = (blockIdx.x * 256 + threadIdx.x) >> 5;
    const int lane  = threadIdx.x & 31;
    const size_t p  = (size_t)gwarp;
    const int b     = (int)(p >> 14);

    const int*   ip = idx + p * 3;
    const float* wp = wt  + p * 3;
    int   j0 = ip[0], j1 = ip[1], j2 = ip[2];
    float w0 = wp[0], w1v = wp[1], w2v = wp[2];

    char* hbase = (char*)(chi + p * CIN);
    char* lbase = (char*)(clo + p * CIN);
    const float4* f4 = (const float4*)(ffeat + p * CF);

    {   // channels [0,128): fine_feat copy (split)
        float4 v = f4[lane];
        uint32_t h0, l0, h1, l1;
        split2(v.x, v.y, h0, l0); split2(v.z, v.w, h1, l1);
        *(uint2*)(hbase + lane * 8) = make_uint2(h0, h1);
        *(uint2*)(lbase + lane * 8) = make_uint2(l0, l1);
    }
    const float4* c0 = (const float4*)(cfeat + ((size_t)b * SPTS + j0) * CC);
    const float4* c1 = (const float4*)(cfeat + ((size_t)b * SPTS + j1) * CC);
    const float4* c2 = (const float4*)(cfeat + ((size_t)b * SPTS + j2) * CC);
    #pragma unroll
    for (int t = 0; t < 2; t++) {
        int c = t * 32 + lane;
        float4 A = c0[c], B = c1[c], Cv = c2[c];
        float4 r;
        r.x = w0*A.x + w1v*B.x + w2v*Cv.x;
        r.y = w0*A.y + w1v*B.y + w2v*Cv.y;
        r.z = w0*A.z + w1v*B.z + w2v*Cv.z;
        r.w = w0*A.w + w1v*B.w + w2v*Cv.w;
        uint32_t h0, l0, h1, l1;
        split2(r.x, r.y, h0, l0); split2(r.z, r.w, h1, l1);
        *(uint2*)(hbase + 256 + c * 8) = make_uint2(h0, h1);
        *(uint2*)(lbase + 256 + c * 8) = make_uint2(l0, l1);
    }
}

// ==================== GEMM1: mma.sync fp16x3 + fused GN1 partial stats ====================
// C[65536,192] = A[65536,384] @ W1[192,384]^T ; CTA 128x192, warps 2x4 (64x48), BK=32
// SMEM tiles padded to stride 40 halves (80 B, 16B-aligned, ldmatrix conflict-free)
#define G1_AH 0
#define G1_AL 10240
#define G1_BH 20480
#define G1_BL 35840
#define G1_SMEM 51200

__global__ void __launch_bounds__(256) gemm1_mma(
    const __half* __restrict__ Ah, const __half* __restrict__ Al,
    const __half* __restrict__ Bh, const __half* __restrict__ Bl,
    float* __restrict__ C, float* __restrict__ part)
{
    extern __shared__ char smem[];
    const uint32_t sb = smem_u32(smem);
    const int tid = threadIdx.x, lane = tid & 31, wid = tid >> 5;
    const int wm = wid & 1, wn = wid >> 1;           // warp grid 2 x 4
    const int m0 = blockIdx.x * 128;

    const int arow = tid >> 1, akoff = (tid & 1) * 16;   // A: 16 halves/thread

    float acc[4][6][4];
    #pragma unroll
    for (int i = 0; i < 4; i++)
        #pragma unroll
        for (int j = 0; j < 6; j++)
            #pragma unroll
            for (int k = 0; k < 4; k++) acc[i][j][k] = 0.0f;

    uint4 aH[2], aL[2], bH[3], bL[3];
    auto loadG = [&](int it) {
        int kc0 = it * 32;
        const uint4* pH = (const uint4*)(Ah + (size_t)(m0 + arow) * CIN + kc0 + akoff);
        const uint4* pL = (const uint4*)(Al + (size_t)(m0 + arow) * CIN + kc0 + akoff);
        aH[0] = pH[0]; aH[1] = pH[1];
        aL[0] = pL[0]; aL[1] = pL[1];
        #pragma unroll
        for (int q = 0; q < 3; q++) {
            int idx = q * 256 + tid;
            int br = idx >> 2, bk = (idx & 3) * 8;
            bH[q] = *(const uint4*)(Bh + (size_t)br * CIN + kc0 + bk);
            bL[q] = *(const uint4*)(Bl + (size_t)br * CIN + kc0 + bk);
        }
    };
    auto storeS = [&]() {
        *(uint4*)(smem + G1_AH + arow * 80 + akoff * 2)      = aH[0];
        *(uint4*)(smem + G1_AH + arow * 80 + akoff * 2 + 16) = aH[1];
        *(uint4*)(smem + G1_AL + arow * 80 + akoff * 2)      = aL[0];
        *(uint4*)(smem + G1_AL + arow * 80 + akoff * 2 + 16) = aL[1];
        #pragma unroll
        for (int q = 0; q < 3; q++) {
            int idx = q * 256 + tid;
            int br = idx >> 2, bk = (idx & 3) * 8;
            *(uint4*)(smem + G1_BH + br * 80 + bk * 2) = bH[q];
            *(uint4*)(smem + G1_BL + br * 80 + bk * 2) = bL[q];
        }
    };

    const int lrow = lane & 15, lk = (lane >> 4) * 8;
    loadG(0);
    for (int it = 0; it < 12; it++) {
        storeS();
        __syncthreads();
        if (it < 11) loadG(it + 1);
        #pragma unroll
        for (int s = 0; s < 2; s++) {
            const int kc = s * 16;
            uint32_t fAh[4][4], fAl[4][4];
            #pragma unroll
            for (int mf = 0; mf < 4; mf++) {
                uint32_t off = (uint32_t)(((wm * 64 + mf * 16 + lrow) * 40 + kc + lk) * 2);
                LDSM4(fAh[mf][0], fAh[mf][1], fAh[mf][2], fAh[mf][3], sb + G1_AH + off);
                LDSM4(fAl[mf][0], fAl[mf][1], fAl[mf][2], fAl[mf][3], sb + G1_AL + off);
            }
            uint32_t fBh[6][2], fBl[6][2];
            #pragma unroll
            for (int q = 0; q < 3; q++) {
                uint32_t off = (uint32_t)(((wn * 48 + q * 16 + lrow) * 40 + kc + lk) * 2);
                uint32_t r0, r1, r2, r3;
                LDSM4(r0, r1, r2, r3, sb + G1_BH + off);
                fBh[q*2][0] = r0; fBh[q*2][1] = r2;
                fBh[q*2+1][0] = r1; fBh[q*2+1][1] = r3;
                LDSM4(r0, r1, r2, r3, sb + G1_BL + off);
                fBl[q*2][0] = r0; fBl[q*2][1] = r2;
                fBl[q*2+1][0] = r1; fBl[q*2+1][1] = r3;
            }
            #pragma unroll
            for (int mf = 0; mf < 4; mf++)
                #pragma unroll
                for (int nf = 0; nf < 6; nf++) {
                    MMA16816(acc[mf][nf], fAh[mf][0], fAh[mf][1], fAh[mf][2], fAh[mf][3],
                             fBh[nf][0], fBh[nf][1]);
                    MMA16816(acc[mf][nf], fAh[mf][0], fAh[mf][1], fAh[mf][2], fAh[mf][3],
                             fBl[nf][0], fBl[nf][1]);
                    MMA16816(acc[mf][nf], fAl[mf][0], fAl[mf][1], fAl[mf][2], fAl[mf][3],
                             fBh[nf][0], fBh[nf][1]);
                }
        }
        __syncthreads();
    }

    // epilogue: write C + GN1 partial stats from accumulators
    const int g = lane >> 2, tig = lane & 3;
    float gs[16];
    #pragma unroll
    for (int i = 0; i < 16; i++) gs[i] = 0.0f;
    #pragma unroll
    for (int mf = 0; mf < 4; mf++)
        #pragma unroll
        for (int nf = 0; nf < 6; nf++) {
            int row = m0 + wm * 64 + mf * 16 + g;
            int col = wn * 48 + nf * 8 + tig * 2;
            float d0 = acc[mf][nf][0], d1 = acc[mf][nf][1];
            float d2 = acc[mf][nf][2], d3 = acc[mf][nf][3];
            *(float2*)(C + (size_t)row * CMID + col)       = make_float2(d0, d1);
            *(float2*)(C + (size_t)(row + 8) * CMID + col) = make_float2(d2, d3);
            int grp = col / 24;   // col even; col & col+1 always same group
            gs[grp]     += d0 + d1 + d2 + d3;
            gs[8 + grp] += d0*d0 + d1*d1 + d2*d2 + d3*d3;
        }
    __syncthreads();
    float* red = (float*)smem;
    #pragma unroll
    for (int i = 0; i < 16; i++) red[i * 256 + tid] = gs[i];
    __syncthreads();
    for (int off = 128; off > 0; off >>= 1) {
        if (tid < off) {
            #pragma unroll
            for (int i = 0; i < 16; i++) red[i * 256 + tid] += red[i * 256 + tid + off];
        }
        __syncthreads();
    }
    if (tid < 16) {
        int b = blockIdx.x >> 7, cta = blockIdx.x & 127;
        int grp = tid & 7;
        part[(tid >= 8 ? 4096 : 0) + (b * 8 + grp) * 128 + cta] = red[tid * 256];
    }
}

// ==================== GEMM2: mma.sync fp16x3 (GN1 affine+relu fused) + GN2 stats ====================
// out[65536,128] = relu(gn1(h1))[65536,192] @ W2[128,192]^T ; CTA 128x128, warps 2x4 (64x32), BK=32
#define G2_AH 0
#define G2_AL 10240
#define G2_BH 20480
#define G2_BL 30720
#define G2_AFF 40960
#define G2_SMEM (G2_AFF + 2 * CMID * 4)

__global__ void __launch_bounds__(256) gemm2_mma(
    const float* __restrict__ H,
    const __half* __restrict__ Bh, const __half* __restrict__ Bl,
    const float* __restrict__ a1, const float* __restrict__ b1,
    float* __restrict__ Out, float* __restrict__ part)
{
    extern __shared__ char smem[];
    const uint32_t sb = smem_u32(smem);
    const int tid = threadIdx.x, lane = tid & 31, wid = tid >> 5;
    const int wm = wid & 1, wn = wid >> 1;
    const int m0 = blockIdx.x * 128;
    const int bb = blockIdx.x >> 7;

    float* s_a = (float*)(smem + G2_AFF);
    float* s_b = s_a + CMID;
    for (int i = tid; i < CMID; i += 256) { s_a[i] = a1[bb * CMID + i]; s_b[i] = b1[bb * CMID + i]; }
    __syncthreads();

    const int arow = tid >> 1, akoff = (tid & 1) * 16;

    float acc[4][4][4];
    #pragma unroll
    for (int i = 0; i < 4; i++)
        #pragma unroll
        for (int j = 0; j < 4; j++)
            #pragma unroll
            for (int k = 0; k < 4; k++) acc[i][j][k] = 0.0f;

    uint4 aH[2], aL[2], bH[2], bL[2];
    auto loadG = [&](int it) {
        int kc0 = it * 32;
        const float* hrow = H + (size_t)(m0 + arow) * CMID + kc0 + akoff;
        uint32_t hq[8], lq[8];
        #pragma unroll
        for (int e = 0; e < 8; e++) {
            int c = kc0 + akoff + e * 2;
            float x = fmaxf(fmaf(hrow[e*2],   s_a[c],   s_b[c]),   0.0f);
            float y = fmaxf(fmaf(hrow[e*2+1], s_a[c+1], s_b[c+1]), 0.0f);
            split2(x, y, hq[e], lq[e]);
        }
        aH[0] = make_uint4(hq[0], hq[1], hq[2], hq[3]);
        aH[1] = make_uint4(hq[4], hq[5], hq[6], hq[7]);
        aL[0] = make_uint4(lq[0], lq[1], lq[2], lq[3]);
        aL[1] = make_uint4(lq[4], lq[5], lq[6], lq[7]);
        // B: same mapping (128 rows)
        bH[0] = *(const uint4*)(Bh + (size_t)arow * CMID + kc0 + akoff);
        bH[1] = *(const uint4*)(Bh + (size_t)arow * CMID + kc0 + akoff + 8);
        bL[0] = *(const uint4*)(Bl + (size_t)arow * CMID + kc0 + akoff);
        bL[1] = *(const uint4*)(Bl + (size_t)arow * CMID + kc0 + akoff + 8);
    };
    auto storeS = [&]() {
        *(uint4*)(smem + G2_AH + arow * 80 + akoff * 2)      = aH[0];
        *(uint4*)(smem + G2_AH + arow * 80 + akoff * 2 + 16) = aH[1];
        *(uint4*)(smem + G2_AL + arow * 80 + akoff * 2)      = aL[0];
        *(uint4*)(smem + G2_AL + arow * 80 + akoff * 2 + 16) = aL[1];
        *(uint4*)(smem + G2_BH + arow * 80 + akoff * 2)      = bH[0];
        *(uint4*)(smem + G2_BH + arow * 80 + akoff * 2 + 16) = bH[1];
        *(uint4*)(smem + G2_BL + arow * 80 + akoff * 2)      = bL[0];
        *(uint4*)(smem + G2_BL + arow * 80 + akoff * 2 + 16) = bL[1];
    };

    const int lrow = lane & 15, lk = (lane >> 4) * 8;
    loadG(0);
    for (int it = 0; it < 6; it++) {
        storeS();
        __syncthreads();
        if (it < 5) loadG(it + 1);
        #pragma unroll
        for (int s = 0; s < 2; s++) {
            const int kc = s * 16;
            uint32_t fAh[4][4], fAl[4][4];
            #pragma unroll
            for (int mf = 0; mf < 4; mf++) {
                uint32_t off = (uint32_t)(((wm * 64 + mf * 16 + lrow) * 40 + kc + lk) * 2);
                LDSM4(fAh[mf][0], fAh[mf][1], fAh[mf][2], fAh[mf][3], sb + G2_AH + off);
                LDSM4(fAl[mf][0], fAl[mf][1], fAl[mf][2], fAl[mf][3], sb + G2_AL + off);
            }
            uint32_t fBh[4][2], fBl[4][2];
            #pragma unroll
            for (int q = 0; q < 2; q++) {
                uint32_t off = (uint32_t)(((wn * 32 + q * 16 + lrow) * 40 + kc + lk) * 2);
                uint32_t r0, r1, r2, r3;
                LDSM4(r0, r1, r2, r3, sb + G2_BH + off);
                fBh[q*2][0] = r0; fBh[q*2][1] = r2;
                fBh[q*2+1][0] = r1; fBh[q*2+1][1] = r3;
                LDSM4(r0, r1, r2, r3, sb + G2_BL + off);
                fBl[q*2][0] = r0; fBl[q*2][1] = r2;
                fBl[q*2+1][0] = r1; fBl[q*2+1][1] = r3;
            }
            #pragma unroll
            for (int mf = 0; mf < 4; mf++)
                #pragma unroll
                for (int nf = 0; nf < 4; nf++) {
                    MMA16816(acc[mf][nf], fAh[mf][0], fAh[mf][1], fAh[mf][2], fAh[mf][3],
                             fBh[nf][0], fBh[nf][1]);
                    MMA16816(acc[mf][nf], fAh[mf][0], fAh[mf][1], fAh[mf][2], fAh[mf][3],
                             fBl[nf][0], fBl[nf][1]);
                    MMA16816(acc[mf][nf], fAl[mf][0], fAl[mf][1], fAl[mf][2], fAl[mf][3],
                             fBh[nf][0], fBh[nf][1]);
                }
        }
        __syncthreads();
    }

    // epilogue: write Out + GN2 partial stats
    const int g = lane >> 2, tig = lane & 3;
    float gs[16];
    #pragma unroll
    for (int i = 0; i < 16; i++) gs[i] = 0.0f;
    #pragma unroll
    for (int mf = 0; mf < 4; mf++)
        #pragma unroll
        for (int nf = 0; nf < 4; nf++) {
            int row = m0 + wm * 64 + mf * 16 + g;
            int col = wn * 32 + nf * 8 + tig * 2;
            float d0 = acc[mf][nf][0], d1 = acc[mf][nf][1];
            float d2 = acc[mf][nf][2], d3 = acc[mf][nf][3];
            *(float2*)(Out + (size_t)row * COUT + col)       = make_float2(d0, d1);
            *(float2*)(Out + (size_t)(row + 8) * COUT + col) = make_float2(d2, d3);
            int grp = col >> 4;
            gs[grp]     += d0 + d1 + d2 + d3;
            gs[8 + grp] += d0*d0 + d1*d1 + d2*d2 + d3*d3;
        }
    __syncthreads();
    float* red = (float*)smem;
    #pragma unroll
    for (int i = 0; i < 16; i++) red[i * 256 + tid] = gs[i];
    __syncthreads();
    for (int off = 128; off > 0; off >>= 1) {
        if (tid < off) {
            #pragma unroll
            for (int i = 0; i < 16; i++) red[i * 256 + tid] += red[i * 256 + tid + off];
        }
        __syncthreads();
    }
    if (tid < 16) {
        int cta = blockIdx.x & 127;
        int grp = tid & 7;
        part[(tid >= 8 ? 4096 : 0) + (bb * 8 + grp) * 128 + cta] = red[tid * 256];
    }
}

// ==================== GN final: per-channel affine from per-CTA partials ====================
template<int CPG>
__global__ void stats_final(
    const float* __restrict__ ps, const float* __restrict__ pss,
    const float* __restrict__ gamma, const float* __restrict__ beta,
    float* __restrict__ ac, float* __restrict__ bc, int Cdim)
{
    const int bg = blockIdx.x;
    const int b = bg >> 3, g = bg & 7;
    __shared__ float s_m, s_i;
    if (threadIdx.x == 0) {
        float s = 0.0f, ss = 0.0f;
        for (int i = 0; i < 128; i++) { s += ps[bg * 128 + i]; ss += pss[bg * 128 + i]; }
        float cnt = (float)NPTS * (float)CPG;
        float mu = s / cnt;
        float var = ss / cnt - mu * mu;
        s_m = mu; s_i = rsqrtf(var + EPS_GN);
    }
    __syncthreads();
    int ch = g * CPG + threadIdx.x;
    float a = gamma[ch] * s_i;
    ac[b * Cdim + ch] = a;
    bc[b * Cdim + ch] = beta[ch] - s_m * a;
}

// ==================== finalize: out = relu(h2 * a2 + b2) in place ====================
__global__ void __launch_bounds__(256) finalize_kernel(
    float* __restrict__ out, const float* __restrict__ a, const float* __restrict__ bc)
{
    size_t i = (size_t)blockIdx.x * 256 + threadIdx.x;
    int c = (int)(i & 127);
    int b = (int)(i >> 21);
    float v = out[i];
    out[i] = fmaxf(fmaf(v, a[b * COUT + c], bc[b * COUT + c]), 0.0f);
}

// ==================== launch ====================
extern "C" void kernel_launch(void* const* d_in, const int* in_sizes, int n_in,
                              void* d_out, int out_size)
{
    const float* fine_xyz    = (const float*)d_in[0];
    const float* coarse_xyz  = (const float*)d_in[1];
    const float* fine_feat   = (const float*)d_in[2];
    const float* coarse_feat = (const float*)d_in[3];
    const float* w1          = (const float*)d_in[4];
    const float* g1_w        = (const float*)d_in[5];
    const float* g1_b        = (const float*)d_in[6];
    const float* w2          = (const float*)d_in[7];
    const float* g2_w        = (const float*)d_in[8];
    const float* g2_b        = (const float*)d_in[9];
    float* out = (float*)d_out;

    __half *chi, *clo, *w1h, *w1l, *w2h, *w2l;
    float *h1, *wt, *part1, *part2, *a1, *b1, *a2, *b2;
    int* idx;
    cudaGetSymbolAddress((void**)&chi, g_comb_hi);
    cudaGetSymbolAddress((void**)&clo, g_comb_lo);
    cudaGetSymbolAddress((void**)&h1, g_h1);
    cudaGetSymbolAddress((void**)&idx, g_idx);
    cudaGetSymbolAddress((void**)&wt, g_wt);
    cudaGetSymbolAddress((void**)&w1h, g_w1h);
    cudaGetSymbolAddress((void**)&w1l, g_w1l);
    cudaGetSymbolAddress((void**)&w2h, g_w2h);
    cudaGetSymbolAddress((void**)&w2l, g_w2l);
    cudaGetSymbolAddress((void**)&part1, g_part1);
    cudaGetSymbolAddress((void**)&part2, g_part2);
    cudaGetSymbolAddress((void**)&a1, g_a1);
    cudaGetSymbolAddress((void**)&b1, g_b1);
    cudaGetSymbolAddress((void**)&a2, g_a2);
    cudaGetSymbolAddress((void**)&b2, g_b2);

    cudaFuncSetAttribute(gemm1_mma, cudaFuncAttributeMaxDynamicSharedMemorySize, G1_SMEM);
    cudaFuncSetAttribute(gemm2_mma, cudaFuncAttributeMaxDynamicSharedMemorySize, G2_SMEM);

    knn_kernel<<<dim3(NPTS / 128, BATCH), 128>>>(fine_xyz, coarse_xyz, idx, wt);
    prep_weights<<<(CMID * CIN + COUT * CMID + 255) / 256, 256>>>(w1, w2, w1h, w1l, w2h, w2l);
    interp_kernel<<<BN_TOTAL / 8, 256>>>(fine_feat, coarse_feat, idx, wt, chi, clo);
    gemm1_mma<<<BN_TOTAL / 128, 256, G1_SMEM>>>(chi, clo, w1h, w1l, h1, part1);
    stats_final<CMID / GROUPS><<<BATCH * GROUPS, CMID / GROUPS>>>(part1, part1 + 4096, g1_w, g1_b, a1, b1, CMID);
    gemm2_mma<<<BN_TOTAL / 128, 256, G2_SMEM>>>(h1, w2h, w2l, a1, b1, out, part2);
    stats_final<COUT / GROUPS><<<BATCH * GROUPS, COUT / GROUPS>>>(part2, part2 + 4096, g2_w, g2_b, a2, b2, COUT);
    finalize_kernel<<<(BN_TOTAL * COUT) / 256, 256>>>(out, a2, b2);
}